// round 14
// baseline (speedup 1.0000x reference)
#include <cuda_runtime.h>
#include <cstdint>

#define USER_NUM 50000
#define ITEM_NUM 50000
#define NTOT     100000
#define VT_DIM   512
#define CAT_DIM  32
#define HID      128
#define OUTD     64
#define EMAX     2000000

// ---------------- static scratch (no allocs allowed) ----------------
__device__ float g_x0[(size_t)NTOT * HID];
__device__ float g_h1[(size_t)NTOT * HID];
__device__ float g_s1[(size_t)NTOT * HID];
__device__ float g_r1[(size_t)NTOT * HID];
__device__ float g_x1[(size_t)NTOT * HID];
__device__ float g_h2[(size_t)NTOT * OUTD];
__device__ float g_s2[(size_t)NTOT * OUTD];
__device__ float g_r2[(size_t)NTOT * OUTD];
__device__ float g_cat[(size_t)ITEM_NUM * CAT_DIM];
__device__ int   g_cnt[NTOT];
__device__ int   g_fill[NTOT];
__device__ int   g_rowptr[NTOT];
__device__ int   g_csr_src[EMAX];
__device__ int   g_bsum[256];
__device__ int   g_boff[256];

#define SCAN_B 512
#define SCAN_NB ((NTOT + SCAN_B - 1) / SCAN_B)

// ---------------- helpers ----------------
__device__ __forceinline__ void ffma2(unsigned long long& d,
                                      unsigned long long a,
                                      unsigned long long b) {
    asm("fma.rn.f32x2 %0, %1, %2, %0;" : "+l"(d) : "l"(a), "l"(b));
}
__device__ __forceinline__ void unpack2(unsigned long long v, float& lo, float& hi) {
    asm("mov.b64 {%0, %1}, %2;" : "=f"(lo), "=f"(hi) : "l"(v));
}

// ---------------- init: zero cnt/fill + copy user rows into x0 --------------
__global__ void init_kernel(const float* __restrict__ user) {
    size_t nu = (size_t)USER_NUM * HID / 4;
    size_t stride = (size_t)gridDim.x * blockDim.x;
    size_t gid = (size_t)blockIdx.x * blockDim.x + threadIdx.x;
    for (size_t i = gid; i < NTOT; i += stride) { g_cnt[i] = 0; g_fill[i] = 0; }
    for (size_t i = gid; i < nu; i += stride)
        ((float4*)g_x0)[i] = ((const float4*)user)[i];
}

// ---------------- embedding bag ----------------
__global__ void catbag_kernel(const float* __restrict__ table,
                              const int* __restrict__ idx,
                              const int* __restrict__ offs,
                              int tot_idx) {
    int gid = blockIdx.x * blockDim.x + threadIdx.x;
    if (gid >= ITEM_NUM * 8) return;
    int bag  = gid >> 3;
    int comp = (gid & 7) * 4;
    int beg = offs[bag];
    int end = (bag + 1 < ITEM_NUM) ? offs[bag + 1] : tot_idx;
    float4 s = make_float4(0.f, 0.f, 0.f, 0.f);
    for (int j = beg; j < end; j++) {
        int ix = __ldg(&idx[j]);
        float4 t = *(const float4*)(table + (size_t)ix * CAT_DIM + comp);
        s.x += t.x; s.y += t.y; s.z += t.z; s.w += t.w;
    }
    float inv = 1.0f / (float)max(end - beg, 1);
    s.x *= inv; s.y *= inv; s.z *= inv; s.w *= inv;
    *(float4*)(g_cat + (size_t)bag * CAT_DIM + comp) = s;
}

// ---------------- CSR build ----------------
__global__ void count_kernel(const int* __restrict__ dst, int E) {
    int stride = gridDim.x * blockDim.x;
    for (int e = blockIdx.x * blockDim.x + threadIdx.x; e < E; e += stride)
        atomicAdd(&g_cnt[__ldg(&dst[e])], 1);
}

__global__ void scan1_kernel() {
    __shared__ int sm[SCAN_B];
    int t = threadIdx.x;
    int i = blockIdx.x * SCAN_B + t;
    int v = (i < NTOT) ? g_cnt[i] : 0;
    sm[t] = v;
    __syncthreads();
#pragma unroll
    for (int off = 1; off < SCAN_B; off <<= 1) {
        int x = (t >= off) ? sm[t - off] : 0;
        __syncthreads();
        sm[t] += x;
        __syncthreads();
    }
    if (i < NTOT) g_rowptr[i] = sm[t] - v;
    if (t == SCAN_B - 1) g_bsum[blockIdx.x] = sm[t];
}

__global__ void scan2_kernel() {
    __shared__ int sm[256];
    int t = threadIdx.x;
    int v = (t < SCAN_NB) ? g_bsum[t] : 0;
    sm[t] = v;
    __syncthreads();
#pragma unroll
    for (int off = 1; off < 256; off <<= 1) {
        int x = (t >= off) ? sm[t - off] : 0;
        __syncthreads();
        sm[t] += x;
        __syncthreads();
    }
    if (t < SCAN_NB) g_boff[t] = sm[t] - v;
}

__global__ void scan3_kernel() {
    int i = blockIdx.x * SCAN_B + threadIdx.x;
    if (i < NTOT) g_rowptr[i] += g_boff[blockIdx.x];
}

__global__ void fill_kernel(const int* __restrict__ src,
                            const int* __restrict__ dst, int E) {
    int stride = gridDim.x * blockDim.x;
    for (int e = blockIdx.x * blockDim.x + threadIdx.x; e < E; e += stride) {
        int d = __ldg(&dst[e]);
        int pos = g_rowptr[d] + atomicAdd(&g_fill[d], 1);
        g_csr_src[pos] = __ldg(&src[e]);
    }
}

// ---------------- CSR gather-aggregate (R10 2-edge unroll) ----------------
template <int NC>
__global__ void agg_kernel(const float* __restrict__ h, float* __restrict__ s) {
    constexpr int LPE = NC / 4;
    int gt = blockIdx.x * blockDim.x + threadIdx.x;
    int node = gt / LPE;
    int lane = threadIdx.x & (LPE - 1);
    if (node >= NTOT) return;
    int co = lane * 4;
    int beg = __ldg(&g_rowptr[node]);
    int end = beg + __ldg(&g_cnt[node]);
    float4 acc = make_float4(0.f, 0.f, 0.f, 0.f);
    int j = beg;
    for (; j + 1 < end; j += 2) {
        int s0 = __ldg(&g_csr_src[j]);
        int s1 = __ldg(&g_csr_src[j + 1]);
        float4 v0 = *(const float4*)(h + (size_t)s0 * NC + co);
        float4 v1 = *(const float4*)(h + (size_t)s1 * NC + co);
        acc.x += v0.x + v1.x; acc.y += v0.y + v1.y;
        acc.z += v0.z + v1.z; acc.w += v0.w + v1.w;
    }
    if (j < end) {
        int s0 = __ldg(&g_csr_src[j]);
        float4 v0 = *(const float4*)(h + (size_t)s0 * NC + co);
        acc.x += v0.x; acc.y += v0.y; acc.z += v0.z; acc.w += v0.w;
    }
    *(float4*)(s + (size_t)node * NC + co) = acc;
}

// ---------------- combine: out = [leaky](s/deg + b + r) ---------------------
template <int NC, bool LEAKY>
__global__ void combine_kernel(const float* __restrict__ s,
                               const float* __restrict__ r,
                               const float* __restrict__ bias,
                               float* __restrict__ out) {
    constexpr int LPN = NC / 4;
    size_t gid = (size_t)blockIdx.x * blockDim.x + threadIdx.x;
    if (gid >= (size_t)NTOT * LPN) return;
    int node = gid / LPN;
    int c = (gid % LPN) * 4;
    float dinv = 1.0f / fmaxf((float)__ldg(&g_cnt[node]), 1.0f);
    float4 sv = ((const float4*)s)[gid];
    float4 rv = ((const float4*)r)[gid];
    float4 bv = *(const float4*)(bias + c);
    float4 v;
    v.x = sv.x * dinv + bv.x + rv.x;
    v.y = sv.y * dinv + bv.y + rv.y;
    v.z = sv.z * dinv + bv.z + rv.z;
    v.w = sv.w * dinv + bv.w + rv.w;
    if (LEAKY) {
        v.x = v.x > 0.f ? v.x : 0.01f * v.x;
        v.y = v.y > 0.f ? v.y : 0.01f * v.y;
        v.z = v.z > 0.f ? v.z : 0.01f * v.z;
        v.w = v.w > 0.f ? v.w : 0.01f * v.w;
    }
    ((float4*)out)[gid] = v;
}

// ---- MOV-free FFMA2 GEMM: C[M,NC] = A[M,K] @ W[NC,K]^T ---------------------
// Row-pair packed accumulators; transposed A tile (natural row-pair LDS);
// W tile stored value-duplicated + k-pair interleaved (one LDS.128 = both
// packed W operands for a column). Zero pack MOVs in the inner loop.
template <int NC, bool FUSED>
__global__ __launch_bounds__(256, 2)
void gemm_kernel(const float* __restrict__ A, int K,
                 const float* __restrict__ A2,
                 const float* __restrict__ W,
                 float* __restrict__ C, int M) {
    constexpr int BM = 128, BK = 16;
    constexpr int WPT = NC / 64;          // W float4 loads per thread (2 or 1)
    constexpr int NG  = NC / 16;          // column groups (8 or 4)
    constexpr int AST = BM + 4;           // AsT row stride (132 floats)
    constexpr int WST = NC * 4 + 4;       // WsI row stride (floats)

    __shared__ float AsT[2][BK][AST];     // transposed A: AsT[k][m]
    __shared__ float WsI[2][BK / 2][WST]; // dup+interleaved W: [k2][4c]={we,we,wo,wo}

    int tid = threadIdx.x;
    int tx = tid & 15, ty = tid >> 4;
    int row0 = blockIdx.x * BM;
    int r0 = ty * 8;

    unsigned long long acc2[4][NG];       // {C[r0+2rp][c], C[r0+2rp+1][c]}
#pragma unroll
    for (int rp = 0; rp < 4; rp++)
#pragma unroll
        for (int g = 0; g < NG; g++) acc2[rp][g] = 0ull;

    float4 ar[2], wr[WPT];
    int nch = K / BK;

    auto ldgA = [&](int ch) {
        int kk = ch * BK;
#pragma unroll
        for (int h = 0; h < 2; h++) {
            int f = tid + h * 256;
            int row = f >> 2;
            int kc = (f & 3) * 4;
            int grow = row0 + row;
            float4 v = make_float4(0.f, 0.f, 0.f, 0.f);
            if (grow < M) {
                if (!FUSED)
                    v = *(const float4*)(A + (size_t)grow * K + kk + kc);
                else if (kk < VT_DIM)
                    v = *(const float4*)(A + (size_t)grow * VT_DIM + kk + kc);
                else
                    v = *(const float4*)(A2 + (size_t)grow * CAT_DIM + (kk - VT_DIM) + kc);
            }
            ar[h] = v;
        }
    };
    auto ldgW = [&](int ch) {
        int kk = ch * BK;
#pragma unroll
        for (int h = 0; h < WPT; h++) {
            int f = tid + h * 256;
            int c = f >> 2;
            int kq = (f & 3) * 4;
            wr[h] = *(const float4*)(W + (size_t)c * K + kk + kq);
        }
    };
    auto sts = [&](int b) {
#pragma unroll
        for (int h = 0; h < 2; h++) {
            int f = tid + h * 256;
            int row = f >> 2;
            int kc = (f & 3) * 4;
            float4 v = ar[h];
            AsT[b][kc + 0][row] = v.x;
            AsT[b][kc + 1][row] = v.y;
            AsT[b][kc + 2][row] = v.z;
            AsT[b][kc + 3][row] = v.w;
        }
#pragma unroll
        for (int h = 0; h < WPT; h++) {
            int f = tid + h * 256;
            int c = f >> 2;
            int k2r = (f & 3) * 2;
            float4 w = wr[h];
            *(float4*)&WsI[b][k2r + 0][c * 4] = make_float4(w.x, w.x, w.y, w.y);
            *(float4*)&WsI[b][k2r + 1][c * 4] = make_float4(w.z, w.z, w.w, w.w);
        }
    };
    auto compute = [&](int b) {
#pragma unroll
        for (int k2 = 0; k2 < BK / 2; k2++) {
            // A row-pairs for even/odd k (broadcast LDS.128, conflict-free)
            ulonglong2 ae01 = *(const ulonglong2*)&AsT[b][2 * k2 + 0][r0];
            ulonglong2 ae23 = *(const ulonglong2*)&AsT[b][2 * k2 + 0][r0 + 4];
            ulonglong2 ao01 = *(const ulonglong2*)&AsT[b][2 * k2 + 1][r0];
            ulonglong2 ao23 = *(const ulonglong2*)&AsT[b][2 * k2 + 1][r0 + 4];
#pragma unroll
            for (int g = 0; g < NG; g++) {
                // one LDS.128: {w_e,w_e} and {w_o,w_o} for col g*16+tx
                ulonglong2 wv = *(const ulonglong2*)&WsI[b][k2][(g * 16 + tx) * 4];
                ffma2(acc2[0][g], ae01.x, wv.x);
                ffma2(acc2[1][g], ae01.y, wv.x);
                ffma2(acc2[2][g], ae23.x, wv.x);
                ffma2(acc2[3][g], ae23.y, wv.x);
                ffma2(acc2[0][g], ao01.x, wv.y);
                ffma2(acc2[1][g], ao01.y, wv.y);
                ffma2(acc2[2][g], ao23.x, wv.y);
                ffma2(acc2[3][g], ao23.y, wv.y);
            }
        }
    };

    ldgA(0); ldgW(0);
    sts(0);
    __syncthreads();

    for (int ch = 0; ch < nch; ch++) {
        int nb = ch & 1;
        if (ch + 1 < nch) { ldgA(ch + 1); ldgW(ch + 1); }
        compute(nb);
        if (ch + 1 < nch) sts(1 - nb);
        __syncthreads();
    }

    // epilogue: scalar stores, 2 rows per accumulator
#pragma unroll
    for (int rp = 0; rp < 4; rp++) {
        int gr = row0 + r0 + 2 * rp;
#pragma unroll
        for (int g = 0; g < NG; g++) {
            float lo, hi;
            unpack2(acc2[rp][g], lo, hi);
            int gc = g * 16 + tx;
            if (gr < M)     C[(size_t)gr * NC + gc] = lo;
            if (gr + 1 < M) C[(size_t)(gr + 1) * NC + gc] = hi;
        }
    }
}

// tiny no-op kernel used as a fork anchor on the capturing stream
__global__ void fork_kernel() {}

// ---------------- launch (R10 schedule) ----------------
extern "C" void kernel_launch(void* const* d_in, const int* in_sizes, int n_in,
                              void* d_out, int out_size) {
    const float* vt      = (const float*)d_in[0];
    const int*   cat_idx = (const int*)d_in[1];
    const int*   cat_off = (const int*)d_in[2];
    const int*   edge    = (const int*)d_in[3];
    const float* cat_tab = (const float*)d_in[4];
    const float* fuse_w  = (const float*)d_in[5];
    const float* user    = (const float*)d_in[6];
    const float* w1_l    = (const float*)d_in[7];
    const float* b1      = (const float*)d_in[8];
    const float* w1_r    = (const float*)d_in[9];
    const float* w2_l    = (const float*)d_in[10];
    const float* b2      = (const float*)d_in[11];
    const float* w2_r    = (const float*)d_in[12];

    int E = in_sizes[3] / 2;
    const int* src = edge;
    const int* dst = edge + E;
    int tot_idx = in_sizes[1];

    float *x0p, *h1p, *s1p, *r1p, *x1p, *h2p, *s2p, *r2p, *catp;
    cudaGetSymbolAddress((void**)&x0p, g_x0);
    cudaGetSymbolAddress((void**)&h1p, g_h1);
    cudaGetSymbolAddress((void**)&s1p, g_s1);
    cudaGetSymbolAddress((void**)&r1p, g_r1);
    cudaGetSymbolAddress((void**)&x1p, g_x1);
    cudaGetSymbolAddress((void**)&h2p, g_h2);
    cudaGetSymbolAddress((void**)&s2p, g_s2);
    cudaGetSymbolAddress((void**)&r2p, g_r2);
    cudaGetSymbolAddress((void**)&catp, g_cat);

    static cudaStream_t sB = nullptr;
    static cudaEvent_t eFork, eH1u, eH1i, eR1, eH2, eR2;
    if (!sB) {
        cudaStreamCreateWithFlags(&sB, cudaStreamNonBlocking);
        cudaEventCreateWithFlags(&eFork, cudaEventDisableTiming);
        cudaEventCreateWithFlags(&eH1u,  cudaEventDisableTiming);
        cudaEventCreateWithFlags(&eH1i,  cudaEventDisableTiming);
        cudaEventCreateWithFlags(&eR1,   cudaEventDisableTiming);
        cudaEventCreateWithFlags(&eH2,   cudaEventDisableTiming);
        cudaEventCreateWithFlags(&eR2,   cudaEventDisableTiming);
    }
    cudaStream_t sA = 0;   // origin (captured) stream

    const int grid_item = (ITEM_NUM + 127) / 128;   // 391
    const int grid_user = (USER_NUM + 127) / 128;   // 391
    const int grid_all  = (NTOT + 127) / 128;       // 782
    const int grid_c1   = (NTOT * (HID / 4) + 255) / 256;
    const int grid_c2   = (NTOT * (OUTD / 4) + 255) / 256;

    // ---- fork: sB joins the capture via an event recorded on sA ----
    fork_kernel<<<1, 32, 0, sA>>>();
    cudaEventRecord(eFork, sA);
    cudaStreamWaitEvent(sB, eFork, 0);

    // ---- side stream: init + CSR build, then user-row halves of h1/r1 ----
    init_kernel<<<1024, 256, 0, sB>>>(user);
    count_kernel<<<2048, 256, 0, sB>>>(dst, E);
    scan1_kernel<<<SCAN_NB, SCAN_B, 0, sB>>>();
    scan2_kernel<<<1, 256, 0, sB>>>();
    scan3_kernel<<<SCAN_NB, SCAN_B, 0, sB>>>();
    fill_kernel<<<2048, 256, 0, sB>>>(src, dst, E);
    gemm_kernel<128, false><<<grid_user, 256, 0, sB>>>(
        x0p, HID, nullptr, w1_l, h1p, USER_NUM);
    cudaEventRecord(eH1u, sB);           // h1 user rows + CSR ready
    gemm_kernel<128, false><<<grid_user, 256, 0, sB>>>(
        x0p, HID, nullptr, w1_r, r1p, USER_NUM);

    // ---- main stream: features ----
    catbag_kernel<<<(ITEM_NUM * 8 + 255) / 256, 256, 0, sA>>>(cat_tab, cat_idx, cat_off, tot_idx);
    gemm_kernel<128, true><<<grid_item, 256, 0, sA>>>(
        vt, VT_DIM + CAT_DIM, catp, fuse_w, x0p + (size_t)USER_NUM * HID, ITEM_NUM);

    // ---- conv1 item halves + aggregate ----
    gemm_kernel<128, false><<<grid_item, 256, 0, sA>>>(
        x0p + (size_t)USER_NUM * HID, HID, nullptr, w1_l,
        h1p + (size_t)USER_NUM * HID, ITEM_NUM);
    cudaEventRecord(eH1i, sA);

    cudaStreamWaitEvent(sB, eH1i, 0);    // x0 item rows ready (and h1 done)
    gemm_kernel<128, false><<<grid_item, 256, 0, sB>>>(
        x0p + (size_t)USER_NUM * HID, HID, nullptr, w1_r,
        r1p + (size_t)USER_NUM * HID, ITEM_NUM);
    cudaEventRecord(eR1, sB);

    cudaStreamWaitEvent(sA, eH1u, 0);    // h1 user rows + CSR ready
    agg_kernel<128><<<(NTOT * 32 + 255) / 256, 256, 0, sA>>>(h1p, s1p);
    cudaStreamWaitEvent(sA, eR1, 0);
    combine_kernel<128, true><<<grid_c1, 256, 0, sA>>>(s1p, r1p, b1, x1p);

    // ---- conv2: h2 alone; then agg2 (mem) ∥ r2 (compute) ----
    gemm_kernel<64, false><<<grid_all, 256, 0, sA>>>(
        x1p, HID, nullptr, w2_l, h2p, NTOT);
    cudaEventRecord(eH2, sA);

    cudaStreamWaitEvent(sB, eH2, 0);     // x1 ready (combine1 precedes eH2 on sA)
    gemm_kernel<64, false><<<grid_all, 256, 0, sB>>>(
        x1p, HID, nullptr, w2_r, r2p, NTOT);
    cudaEventRecord(eR2, sB);

    agg_kernel<64><<<(NTOT * 16 + 255) / 256, 256, 0, sA>>>(h2p, s2p);
    cudaStreamWaitEvent(sA, eR2, 0);     // join: sB fully merged back into sA
    combine_kernel<64, false><<<grid_c2, 256, 0, sA>>>(s2p, r2p, b2, (float*)d_out);
}

// round 15
// speedup vs baseline: 1.1671x; 1.1671x over previous
#include <cuda_runtime.h>
#include <cuda_fp16.h>
#include <cstdint>

#define USER_NUM 50000
#define ITEM_NUM 50000
#define NTOT     100000
#define VT_DIM   512
#define CAT_DIM  32
#define HID      128
#define OUTD     64
#define EMAX     2000000

// ---------------- static scratch (no allocs allowed) ----------------
__device__ float  g_x0[(size_t)NTOT * HID];
__device__ __half g_h1h[(size_t)NTOT * HID];   // fp16 h1 (gather-only tensor)
__device__ float  g_s1[(size_t)NTOT * HID];
__device__ float  g_r1[(size_t)NTOT * HID];
__device__ float  g_x1[(size_t)NTOT * HID];
__device__ float  g_h2[(size_t)NTOT * OUTD];
__device__ float  g_s2[(size_t)NTOT * OUTD];
__device__ float  g_r2[(size_t)NTOT * OUTD];
__device__ float  g_cat[(size_t)ITEM_NUM * CAT_DIM];
__device__ int    g_cnt[NTOT];
__device__ int    g_fill[NTOT];
__device__ int    g_rowptr[NTOT];
__device__ int    g_csr_src[EMAX];
__device__ int    g_bsum[256];
__device__ int    g_boff[256];

#define SCAN_B 512
#define SCAN_NB ((NTOT + SCAN_B - 1) / SCAN_B)

// ---------------- helpers ----------------
__device__ __forceinline__ void ffma2(unsigned long long& d,
                                      unsigned long long a,
                                      unsigned long long b) {
    asm("fma.rn.f32x2 %0, %1, %2, %0;" : "+l"(d) : "l"(a), "l"(b));
}
__device__ __forceinline__ unsigned long long pack_dup(float a) {
    unsigned long long r;
    asm("mov.b64 %0, {%1, %1};" : "=l"(r) : "f"(a));
    return r;
}
__device__ __forceinline__ void unpack2(unsigned long long v, float& lo, float& hi) {
    asm("mov.b64 {%0, %1}, %2;" : "=f"(lo), "=f"(hi) : "l"(v));
}

// ---------------- init: zero cnt/fill + copy user rows into x0 --------------
__global__ void init_kernel(const float* __restrict__ user) {
    size_t nu = (size_t)USER_NUM * HID / 4;
    size_t stride = (size_t)gridDim.x * blockDim.x;
    size_t gid = (size_t)blockIdx.x * blockDim.x + threadIdx.x;
    for (size_t i = gid; i < NTOT; i += stride) { g_cnt[i] = 0; g_fill[i] = 0; }
    for (size_t i = gid; i < nu; i += stride)
        ((float4*)g_x0)[i] = ((const float4*)user)[i];
}

// ---------------- embedding bag ----------------
__global__ void catbag_kernel(const float* __restrict__ table,
                              const int* __restrict__ idx,
                              const int* __restrict__ offs,
                              int tot_idx) {
    int gid = blockIdx.x * blockDim.x + threadIdx.x;
    if (gid >= ITEM_NUM * 8) return;
    int bag  = gid >> 3;
    int comp = (gid & 7) * 4;
    int beg = offs[bag];
    int end = (bag + 1 < ITEM_NUM) ? offs[bag + 1] : tot_idx;
    float4 s = make_float4(0.f, 0.f, 0.f, 0.f);
    for (int j = beg; j < end; j++) {
        int ix = __ldg(&idx[j]);
        float4 t = *(const float4*)(table + (size_t)ix * CAT_DIM + comp);
        s.x += t.x; s.y += t.y; s.z += t.z; s.w += t.w;
    }
    float inv = 1.0f / (float)max(end - beg, 1);
    s.x *= inv; s.y *= inv; s.z *= inv; s.w *= inv;
    *(float4*)(g_cat + (size_t)bag * CAT_DIM + comp) = s;
}

// ---------------- CSR build ----------------
__global__ void count_kernel(const int* __restrict__ dst, int E) {
    int stride = gridDim.x * blockDim.x;
    for (int e = blockIdx.x * blockDim.x + threadIdx.x; e < E; e += stride)
        atomicAdd(&g_cnt[__ldg(&dst[e])], 1);
}

__global__ void scan1_kernel() {
    __shared__ int sm[SCAN_B];
    int t = threadIdx.x;
    int i = blockIdx.x * SCAN_B + t;
    int v = (i < NTOT) ? g_cnt[i] : 0;
    sm[t] = v;
    __syncthreads();
#pragma unroll
    for (int off = 1; off < SCAN_B; off <<= 1) {
        int x = (t >= off) ? sm[t - off] : 0;
        __syncthreads();
        sm[t] += x;
        __syncthreads();
    }
    if (i < NTOT) g_rowptr[i] = sm[t] - v;
    if (t == SCAN_B - 1) g_bsum[blockIdx.x] = sm[t];
}

__global__ void scan2_kernel() {
    __shared__ int sm[256];
    int t = threadIdx.x;
    int v = (t < SCAN_NB) ? g_bsum[t] : 0;
    sm[t] = v;
    __syncthreads();
#pragma unroll
    for (int off = 1; off < 256; off <<= 1) {
        int x = (t >= off) ? sm[t - off] : 0;
        __syncthreads();
        sm[t] += x;
        __syncthreads();
    }
    if (t < SCAN_NB) g_boff[t] = sm[t] - v;
}

__global__ void scan3_kernel() {
    int i = blockIdx.x * SCAN_B + threadIdx.x;
    if (i < NTOT) g_rowptr[i] += g_boff[blockIdx.x];
}

__global__ void fill_kernel(const int* __restrict__ src,
                            const int* __restrict__ dst, int E) {
    int stride = gridDim.x * blockDim.x;
    for (int e = blockIdx.x * blockDim.x + threadIdx.x; e < E; e += stride) {
        int d = __ldg(&dst[e]);
        int pos = g_rowptr[d] + atomicAdd(&g_fill[d], 1);
        g_csr_src[pos] = __ldg(&src[e]);
    }
}

// ---------------- CSR gather-aggregate, fp32 h (2-edge unroll) --------------
template <int NC>
__global__ void agg_kernel(const float* __restrict__ h, float* __restrict__ s) {
    constexpr int LPE = NC / 4;
    int gt = blockIdx.x * blockDim.x + threadIdx.x;
    int node = gt / LPE;
    int lane = threadIdx.x & (LPE - 1);
    if (node >= NTOT) return;
    int co = lane * 4;
    int beg = __ldg(&g_rowptr[node]);
    int end = beg + __ldg(&g_cnt[node]);
    float4 acc = make_float4(0.f, 0.f, 0.f, 0.f);
    int j = beg;
    for (; j + 1 < end; j += 2) {
        int s0 = __ldg(&g_csr_src[j]);
        int s1 = __ldg(&g_csr_src[j + 1]);
        float4 v0 = *(const float4*)(h + (size_t)s0 * NC + co);
        float4 v1 = *(const float4*)(h + (size_t)s1 * NC + co);
        acc.x += v0.x + v1.x; acc.y += v0.y + v1.y;
        acc.z += v0.z + v1.z; acc.w += v0.w + v1.w;
    }
    if (j < end) {
        int s0 = __ldg(&g_csr_src[j]);
        float4 v0 = *(const float4*)(h + (size_t)s0 * NC + co);
        acc.x += v0.x; acc.y += v0.y; acc.z += v0.z; acc.w += v0.w;
    }
    *(float4*)(s + (size_t)node * NC + co) = acc;
}

// ---------------- CSR gather-aggregate, fp16 h (2-edge unroll) --------------
// Each lane covers 8 halves (16B); NC=128 → 16 lanes per node.
template <int NC>
__global__ void agg_half_kernel(const __half* __restrict__ h,
                                float* __restrict__ s) {
    constexpr int LPE = NC / 8;
    int gt = blockIdx.x * blockDim.x + threadIdx.x;
    int node = gt / LPE;
    int lane = threadIdx.x & (LPE - 1);
    if (node >= NTOT) return;
    int co = lane * 8;
    int beg = __ldg(&g_rowptr[node]);
    int end = beg + __ldg(&g_cnt[node]);
    float acc[8];
#pragma unroll
    for (int i = 0; i < 8; i++) acc[i] = 0.f;
    int j = beg;
    for (; j + 1 < end; j += 2) {
        int s0 = __ldg(&g_csr_src[j]);
        int s1 = __ldg(&g_csr_src[j + 1]);
        uint4 u0 = *(const uint4*)(h + (size_t)s0 * NC + co);
        uint4 u1 = *(const uint4*)(h + (size_t)s1 * NC + co);
        const __half2* p0 = (const __half2*)&u0;
        const __half2* p1 = (const __half2*)&u1;
#pragma unroll
        for (int q = 0; q < 4; q++) {
            float2 f0 = __half22float2(p0[q]);
            float2 f1 = __half22float2(p1[q]);
            acc[2 * q + 0] += f0.x + f1.x;
            acc[2 * q + 1] += f0.y + f1.y;
        }
    }
    if (j < end) {
        int s0 = __ldg(&g_csr_src[j]);
        uint4 u0 = *(const uint4*)(h + (size_t)s0 * NC + co);
        const __half2* p0 = (const __half2*)&u0;
#pragma unroll
        for (int q = 0; q < 4; q++) {
            float2 f0 = __half22float2(p0[q]);
            acc[2 * q + 0] += f0.x;
            acc[2 * q + 1] += f0.y;
        }
    }
    *(float4*)(s + (size_t)node * NC + co) =
        make_float4(acc[0], acc[1], acc[2], acc[3]);
    *(float4*)(s + (size_t)node * NC + co + 4) =
        make_float4(acc[4], acc[5], acc[6], acc[7]);
}

// ---------------- combine: out = [leaky](s/deg + b + r) ---------------------
template <int NC, bool LEAKY>
__global__ void combine_kernel(const float* __restrict__ s,
                               const float* __restrict__ r,
                               const float* __restrict__ bias,
                               float* __restrict__ out) {
    constexpr int LPN = NC / 4;
    size_t gid = (size_t)blockIdx.x * blockDim.x + threadIdx.x;
    if (gid >= (size_t)NTOT * LPN) return;
    int node = gid / LPN;
    int c = (gid % LPN) * 4;
    float dinv = 1.0f / fmaxf((float)__ldg(&g_cnt[node]), 1.0f);
    float4 sv = ((const float4*)s)[gid];
    float4 rv = ((const float4*)r)[gid];
    float4 bv = *(const float4*)(bias + c);
    float4 v;
    v.x = sv.x * dinv + bv.x + rv.x;
    v.y = sv.y * dinv + bv.y + rv.y;
    v.z = sv.z * dinv + bv.z + rv.z;
    v.w = sv.w * dinv + bv.w + rv.w;
    if (LEAKY) {
        v.x = v.x > 0.f ? v.x : 0.01f * v.x;
        v.y = v.y > 0.f ? v.y : 0.01f * v.y;
        v.z = v.z > 0.f ? v.z : 0.01f * v.z;
        v.w = v.w > 0.f ? v.w : 0.01f * v.w;
    }
    ((float4*)out)[gid] = v;
}

// ---- pipelined FFMA2 GEMM (R3 config): C[M,NC] = A[M,K] @ W[NC,K]^T --------
// HALF_OUT: write C as fp16 (half2-pair 8B stores) instead of fp32 float4.
template <int NC, bool FUSED, bool HALF_OUT>
__global__ __launch_bounds__(256, 2)
void gemm_kernel(const float* __restrict__ A, int K,
                 const float* __restrict__ A2,
                 const float* __restrict__ W,
                 void* __restrict__ Cout, int M) {
    constexpr int BM = 128, BK = 16;
    constexpr int WPT = NC / 64;
    constexpr int NG  = NC / 64;
    constexpr int CP2 = NC / 32;
    constexpr int WST = NC + 4;

    __shared__ float As[2][BM][BK + 4];
    __shared__ float Ws[2][BK][WST];

    int tid = threadIdx.x;
    int tx = tid & 15, ty = tid >> 4;
    int row0 = blockIdx.x * BM;
    int r0 = ty * 8;
    int c0 = tx * 4;

    unsigned long long acc2[8][CP2];
#pragma unroll
    for (int i = 0; i < 8; i++)
#pragma unroll
        for (int j = 0; j < CP2; j++) acc2[i][j] = 0ull;

    float4 ar[2], wr[WPT];
    int nch = K / BK;

    auto ldgA = [&](int ch) {
        int kk = ch * BK;
#pragma unroll
        for (int h = 0; h < 2; h++) {
            int f = tid + h * 256;
            int row = f >> 2;
            int kc = (f & 3) * 4;
            int grow = row0 + row;
            float4 v = make_float4(0.f, 0.f, 0.f, 0.f);
            if (grow < M) {
                if (!FUSED)
                    v = *(const float4*)(A + (size_t)grow * K + kk + kc);
                else if (kk < VT_DIM)
                    v = *(const float4*)(A + (size_t)grow * VT_DIM + kk + kc);
                else
                    v = *(const float4*)(A2 + (size_t)grow * CAT_DIM + (kk - VT_DIM) + kc);
            }
            ar[h] = v;
        }
    };
    auto ldgW = [&](int ch) {
        int kk = ch * BK;
#pragma unroll
        for (int h = 0; h < WPT; h++) {
            int f = tid + h * 256;
            int c = f >> 2;
            int kq = (f & 3) * 4;
            wr[h] = *(const float4*)(W + (size_t)c * K + kk + kq);
        }
    };
    auto sts = [&](int b) {
#pragma unroll
        for (int h = 0; h < 2; h++) {
            int f = tid + h * 256;
            *(float4*)&As[b][f >> 2][(f & 3) * 4] = ar[h];
        }
#pragma unroll
        for (int h = 0; h < WPT; h++) {
            int f = tid + h * 256;
            int c = f >> 2;
            int kq = (f & 3) * 4;
            Ws[b][kq + 0][c] = wr[h].x;
            Ws[b][kq + 1][c] = wr[h].y;
            Ws[b][kq + 2][c] = wr[h].z;
            Ws[b][kq + 3][c] = wr[h].w;
        }
    };
    auto compute = [&](int b) {
#pragma unroll
        for (int k2 = 0; k2 < BK; k2 += 2) {
            ulonglong2 w0[NG], w1[NG];
#pragma unroll
            for (int g = 0; g < NG; g++) {
                w0[g] = *(const ulonglong2*)&Ws[b][k2 + 0][c0 + g * 64];
                w1[g] = *(const ulonglong2*)&Ws[b][k2 + 1][c0 + g * 64];
            }
#pragma unroll
            for (int i = 0; i < 8; i++) {
                float2 t = *(const float2*)&As[b][r0 + i][k2];
                unsigned long long pa0 = pack_dup(t.x);
                unsigned long long pa1 = pack_dup(t.y);
#pragma unroll
                for (int g = 0; g < NG; g++) {
                    ffma2(acc2[i][2 * g + 0], pa0, w0[g].x);
                    ffma2(acc2[i][2 * g + 1], pa0, w0[g].y);
                    ffma2(acc2[i][2 * g + 0], pa1, w1[g].x);
                    ffma2(acc2[i][2 * g + 1], pa1, w1[g].y);
                }
            }
        }
    };

    ldgA(0); ldgW(0);
    sts(0);
    __syncthreads();

    for (int ch = 0; ch < nch; ch++) {
        int nb = ch & 1;
        if (ch + 1 < nch) { ldgA(ch + 1); ldgW(ch + 1); }
        compute(nb);
        if (ch + 1 < nch) sts(1 - nb);
        __syncthreads();
    }

#pragma unroll
    for (int i = 0; i < 8; i++) {
        int gr = row0 + r0 + i;
        if (gr >= M) continue;
#pragma unroll
        for (int g = 0; g < NG; g++) {
            int gc = c0 + g * 64;
            float4 v;
            unpack2(acc2[i][2 * g + 0], v.x, v.y);
            unpack2(acc2[i][2 * g + 1], v.z, v.w);
            if (HALF_OUT) {
                __half2 p0 = __floats2half2_rn(v.x, v.y);
                __half2 p1 = __floats2half2_rn(v.z, v.w);
                uint2 u;
                u.x = *(unsigned int*)&p0;
                u.y = *(unsigned int*)&p1;
                *(uint2*)((__half*)Cout + (size_t)gr * NC + gc) = u;
            } else {
                *(float4*)((float*)Cout + (size_t)gr * NC + gc) = v;
            }
        }
    }
}

// tiny no-op kernel used as a fork anchor on the capturing stream
__global__ void fork_kernel() {}

// ---------------- launch (R10 schedule) ----------------
extern "C" void kernel_launch(void* const* d_in, const int* in_sizes, int n_in,
                              void* d_out, int out_size) {
    const float* vt      = (const float*)d_in[0];
    const int*   cat_idx = (const int*)d_in[1];
    const int*   cat_off = (const int*)d_in[2];
    const int*   edge    = (const int*)d_in[3];
    const float* cat_tab = (const float*)d_in[4];
    const float* fuse_w  = (const float*)d_in[5];
    const float* user    = (const float*)d_in[6];
    const float* w1_l    = (const float*)d_in[7];
    const float* b1      = (const float*)d_in[8];
    const float* w1_r    = (const float*)d_in[9];
    const float* w2_l    = (const float*)d_in[10];
    const float* b2      = (const float*)d_in[11];
    const float* w2_r    = (const float*)d_in[12];

    int E = in_sizes[3] / 2;
    const int* src = edge;
    const int* dst = edge + E;
    int tot_idx = in_sizes[1];

    float *x0p, *s1p, *r1p, *x1p, *h2p, *s2p, *r2p, *catp;
    __half *h1hp;
    cudaGetSymbolAddress((void**)&x0p, g_x0);
    cudaGetSymbolAddress((void**)&h1hp, g_h1h);
    cudaGetSymbolAddress((void**)&s1p, g_s1);
    cudaGetSymbolAddress((void**)&r1p, g_r1);
    cudaGetSymbolAddress((void**)&x1p, g_x1);
    cudaGetSymbolAddress((void**)&h2p, g_h2);
    cudaGetSymbolAddress((void**)&s2p, g_s2);
    cudaGetSymbolAddress((void**)&r2p, g_r2);
    cudaGetSymbolAddress((void**)&catp, g_cat);

    static cudaStream_t sB = nullptr;
    static cudaEvent_t eFork, eH1u, eH1i, eR1, eH2, eR2;
    if (!sB) {
        cudaStreamCreateWithFlags(&sB, cudaStreamNonBlocking);
        cudaEventCreateWithFlags(&eFork, cudaEventDisableTiming);
        cudaEventCreateWithFlags(&eH1u,  cudaEventDisableTiming);
        cudaEventCreateWithFlags(&eH1i,  cudaEventDisableTiming);
        cudaEventCreateWithFlags(&eR1,   cudaEventDisableTiming);
        cudaEventCreateWithFlags(&eH2,   cudaEventDisableTiming);
        cudaEventCreateWithFlags(&eR2,   cudaEventDisableTiming);
    }
    cudaStream_t sA = 0;   // origin (captured) stream

    const int grid_item = (ITEM_NUM + 127) / 128;   // 391
    const int grid_user = (USER_NUM + 127) / 128;   // 391
    const int grid_all  = (NTOT + 127) / 128;       // 782
    const int grid_c1   = (NTOT * (HID / 4) + 255) / 256;
    const int grid_c2   = (NTOT * (OUTD / 4) + 255) / 256;

    // ---- fork: sB joins the capture via an event recorded on sA ----
    fork_kernel<<<1, 32, 0, sA>>>();
    cudaEventRecord(eFork, sA);
    cudaStreamWaitEvent(sB, eFork, 0);

    // ---- side stream: init + CSR build, then user-row halves of h1/r1 ----
    init_kernel<<<1024, 256, 0, sB>>>(user);
    count_kernel<<<2048, 256, 0, sB>>>(dst, E);
    scan1_kernel<<<SCAN_NB, SCAN_B, 0, sB>>>();
    scan2_kernel<<<1, 256, 0, sB>>>();
    scan3_kernel<<<SCAN_NB, SCAN_B, 0, sB>>>();
    fill_kernel<<<2048, 256, 0, sB>>>(src, dst, E);
    gemm_kernel<128, false, true><<<grid_user, 256, 0, sB>>>(
        x0p, HID, nullptr, w1_l, h1hp, USER_NUM);
    cudaEventRecord(eH1u, sB);           // h1 user rows + CSR ready
    gemm_kernel<128, false, false><<<grid_user, 256, 0, sB>>>(
        x0p, HID, nullptr, w1_r, r1p, USER_NUM);

    // ---- main stream: features ----
    catbag_kernel<<<(ITEM_NUM * 8 + 255) / 256, 256, 0, sA>>>(cat_tab, cat_idx, cat_off, tot_idx);
    gemm_kernel<128, true, false><<<grid_item, 256, 0, sA>>>(
        vt, VT_DIM + CAT_DIM, catp, fuse_w, x0p + (size_t)USER_NUM * HID, ITEM_NUM);

    // ---- conv1 item halves + aggregate ----
    gemm_kernel<128, false, true><<<grid_item, 256, 0, sA>>>(
        x0p + (size_t)USER_NUM * HID, HID, nullptr, w1_l,
        h1hp + (size_t)USER_NUM * HID, ITEM_NUM);
    cudaEventRecord(eH1i, sA);

    cudaStreamWaitEvent(sB, eH1i, 0);    // x0 item rows ready (and h1 done)
    gemm_kernel<128, false, false><<<grid_item, 256, 0, sB>>>(
        x0p + (size_t)USER_NUM * HID, HID, nullptr, w1_r,
        r1p + (size_t)USER_NUM * HID, ITEM_NUM);
    cudaEventRecord(eR1, sB);

    cudaStreamWaitEvent(sA, eH1u, 0);    // h1 user rows + CSR ready
    agg_half_kernel<128><<<(NTOT * 16 + 255) / 256, 256, 0, sA>>>(h1hp, s1p);
    cudaStreamWaitEvent(sA, eR1, 0);
    combine_kernel<128, true><<<grid_c1, 256, 0, sA>>>(s1p, r1p, b1, x1p);

    // ---- conv2: h2 alone; then agg2 (mem) ∥ r2 (compute) ----
    gemm_kernel<64, false, false><<<grid_all, 256, 0, sA>>>(
        x1p, HID, nullptr, w2_l, h2p, NTOT);
    cudaEventRecord(eH2, sA);

    cudaStreamWaitEvent(sB, eH2, 0);     // x1 ready (combine1 precedes eH2 on sA)
    gemm_kernel<64, false, false><<<grid_all, 256, 0, sB>>>(
        x1p, HID, nullptr, w2_r, r2p, NTOT);
    cudaEventRecord(eR2, sB);

    agg_kernel<64><<<(NTOT * 16 + 255) / 256, 256, 0, sA>>>(h2p, s2p);
    cudaStreamWaitEvent(sA, eR2, 0);     // join: sB fully merged back into sA
    combine_kernel<64, false><<<grid_c2, 256, 0, sA>>>(s2p, r2p, b2, (float*)d_out);
}

// round 16
// speedup vs baseline: 1.1807x; 1.0116x over previous
#include <cuda_runtime.h>
#include <cuda_fp16.h>
#include <cstdint>

#define USER_NUM 50000
#define ITEM_NUM 50000
#define NTOT     100000
#define VT_DIM   512
#define CAT_DIM  32
#define HID      128
#define OUTD     64
#define EMAX     2000000

// ---------------- static scratch (no allocs allowed) ----------------
__device__ float  g_x0[(size_t)NTOT * HID];
__device__ __half g_h1h[(size_t)NTOT * HID];   // fp16 h1 (gather-only tensor)
__device__ float  g_s1[(size_t)NTOT * HID];
__device__ float  g_r1[(size_t)NTOT * HID];
__device__ float  g_x1[(size_t)NTOT * HID];
__device__ __half g_h2h[(size_t)NTOT * OUTD];  // fp16 h2 (gather-only tensor)
__device__ float  g_s2[(size_t)NTOT * OUTD];
__device__ float  g_r2[(size_t)NTOT * OUTD];
__device__ float  g_cat[(size_t)ITEM_NUM * CAT_DIM];
__device__ int    g_cnt[NTOT];
__device__ int    g_fill[NTOT];
__device__ int    g_rowptr[NTOT];
__device__ int    g_csr_src[EMAX];
__device__ int    g_bsum[256];
__device__ int    g_boff[256];

#define SCAN_B 512
#define SCAN_NB ((NTOT + SCAN_B - 1) / SCAN_B)

// ---------------- helpers ----------------
__device__ __forceinline__ void ffma2(unsigned long long& d,
                                      unsigned long long a,
                                      unsigned long long b) {
    asm("fma.rn.f32x2 %0, %1, %2, %0;" : "+l"(d) : "l"(a), "l"(b));
}
__device__ __forceinline__ unsigned long long pack_dup(float a) {
    unsigned long long r;
    asm("mov.b64 %0, {%1, %1};" : "=l"(r) : "f"(a));
    return r;
}
__device__ __forceinline__ void unpack2(unsigned long long v, float& lo, float& hi) {
    asm("mov.b64 {%0, %1}, %2;" : "=f"(lo), "=f"(hi) : "l"(v));
}

// ---------------- init: zero cnt/fill + copy user rows into x0 --------------
__global__ void init_kernel(const float* __restrict__ user) {
    size_t nu = (size_t)USER_NUM * HID / 4;
    size_t stride = (size_t)gridDim.x * blockDim.x;
    size_t gid = (size_t)blockIdx.x * blockDim.x + threadIdx.x;
    for (size_t i = gid; i < NTOT; i += stride) { g_cnt[i] = 0; g_fill[i] = 0; }
    for (size_t i = gid; i < nu; i += stride)
        ((float4*)g_x0)[i] = ((const float4*)user)[i];
}

// ---------------- embedding bag ----------------
__global__ void catbag_kernel(const float* __restrict__ table,
                              const int* __restrict__ idx,
                              const int* __restrict__ offs,
                              int tot_idx) {
    int gid = blockIdx.x * blockDim.x + threadIdx.x;
    if (gid >= ITEM_NUM * 8) return;
    int bag  = gid >> 3;
    int comp = (gid & 7) * 4;
    int beg = offs[bag];
    int end = (bag + 1 < ITEM_NUM) ? offs[bag + 1] : tot_idx;
    float4 s = make_float4(0.f, 0.f, 0.f, 0.f);
    for (int j = beg; j < end; j++) {
        int ix = __ldg(&idx[j]);
        float4 t = *(const float4*)(table + (size_t)ix * CAT_DIM + comp);
        s.x += t.x; s.y += t.y; s.z += t.z; s.w += t.w;
    }
    float inv = 1.0f / (float)max(end - beg, 1);
    s.x *= inv; s.y *= inv; s.z *= inv; s.w *= inv;
    *(float4*)(g_cat + (size_t)bag * CAT_DIM + comp) = s;
}

// ---------------- CSR build ----------------
__global__ void count_kernel(const int* __restrict__ dst, int E) {
    int stride = gridDim.x * blockDim.x;
    for (int e = blockIdx.x * blockDim.x + threadIdx.x; e < E; e += stride)
        atomicAdd(&g_cnt[__ldg(&dst[e])], 1);
}

__global__ void scan1_kernel() {
    __shared__ int sm[SCAN_B];
    int t = threadIdx.x;
    int i = blockIdx.x * SCAN_B + t;
    int v = (i < NTOT) ? g_cnt[i] : 0;
    sm[t] = v;
    __syncthreads();
#pragma unroll
    for (int off = 1; off < SCAN_B; off <<= 1) {
        int x = (t >= off) ? sm[t - off] : 0;
        __syncthreads();
        sm[t] += x;
        __syncthreads();
    }
    if (i < NTOT) g_rowptr[i] = sm[t] - v;
    if (t == SCAN_B - 1) g_bsum[blockIdx.x] = sm[t];
}

__global__ void scan2_kernel() {
    __shared__ int sm[256];
    int t = threadIdx.x;
    int v = (t < SCAN_NB) ? g_bsum[t] : 0;
    sm[t] = v;
    __syncthreads();
#pragma unroll
    for (int off = 1; off < 256; off <<= 1) {
        int x = (t >= off) ? sm[t - off] : 0;
        __syncthreads();
        sm[t] += x;
        __syncthreads();
    }
    if (t < SCAN_NB) g_boff[t] = sm[t] - v;
}

__global__ void scan3_kernel() {
    int i = blockIdx.x * SCAN_B + threadIdx.x;
    if (i < NTOT) g_rowptr[i] += g_boff[blockIdx.x];
}

__global__ void fill_kernel(const int* __restrict__ src,
                            const int* __restrict__ dst, int E) {
    int stride = gridDim.x * blockDim.x;
    for (int e = blockIdx.x * blockDim.x + threadIdx.x; e < E; e += stride) {
        int d = __ldg(&dst[e]);
        int pos = g_rowptr[d] + atomicAdd(&g_fill[d], 1);
        g_csr_src[pos] = __ldg(&src[e]);
    }
}

// ---------------- CSR gather-aggregate, fp16 h (2-edge unroll) --------------
// Each lane covers 8 halves (16B); NC=128 → 16 lanes/node, NC=64 → 8.
template <int NC>
__global__ void agg_half_kernel(const __half* __restrict__ h,
                                float* __restrict__ s) {
    constexpr int LPE = NC / 8;
    int gt = blockIdx.x * blockDim.x + threadIdx.x;
    int node = gt / LPE;
    int lane = threadIdx.x & (LPE - 1);
    if (node >= NTOT) return;
    int co = lane * 8;
    int beg = __ldg(&g_rowptr[node]);
    int end = beg + __ldg(&g_cnt[node]);
    float acc[8];
#pragma unroll
    for (int i = 0; i < 8; i++) acc[i] = 0.f;
    int j = beg;
    for (; j + 1 < end; j += 2) {
        int s0 = __ldg(&g_csr_src[j]);
        int s1 = __ldg(&g_csr_src[j + 1]);
        uint4 u0 = *(const uint4*)(h + (size_t)s0 * NC + co);
        uint4 u1 = *(const uint4*)(h + (size_t)s1 * NC + co);
        const __half2* p0 = (const __half2*)&u0;
        const __half2* p1 = (const __half2*)&u1;
#pragma unroll
        for (int q = 0; q < 4; q++) {
            float2 f0 = __half22float2(p0[q]);
            float2 f1 = __half22float2(p1[q]);
            acc[2 * q + 0] += f0.x + f1.x;
            acc[2 * q + 1] += f0.y + f1.y;
        }
    }
    if (j < end) {
        int s0 = __ldg(&g_csr_src[j]);
        uint4 u0 = *(const uint4*)(h + (size_t)s0 * NC + co);
        const __half2* p0 = (const __half2*)&u0;
#pragma unroll
        for (int q = 0; q < 4; q++) {
            float2 f0 = __half22float2(p0[q]);
            acc[2 * q + 0] += f0.x;
            acc[2 * q + 1] += f0.y;
        }
    }
    *(float4*)(s + (size_t)node * NC + co) =
        make_float4(acc[0], acc[1], acc[2], acc[3]);
    *(float4*)(s + (size_t)node * NC + co + 4) =
        make_float4(acc[4], acc[5], acc[6], acc[7]);
}

// ---------------- combine: out = [leaky](s/deg + b + r) ---------------------
template <int NC, bool LEAKY>
__global__ void combine_kernel(const float* __restrict__ s,
                               const float* __restrict__ r,
                               const float* __restrict__ bias,
                               float* __restrict__ out) {
    constexpr int LPN = NC / 4;
    size_t gid = (size_t)blockIdx.x * blockDim.x + threadIdx.x;
    if (gid >= (size_t)NTOT * LPN) return;
    int node = gid / LPN;
    int c = (gid % LPN) * 4;
    float dinv = 1.0f / fmaxf((float)__ldg(&g_cnt[node]), 1.0f);
    float4 sv = ((const float4*)s)[gid];
    float4 rv = ((const float4*)r)[gid];
    float4 bv = *(const float4*)(bias + c);
    float4 v;
    v.x = sv.x * dinv + bv.x + rv.x;
    v.y = sv.y * dinv + bv.y + rv.y;
    v.z = sv.z * dinv + bv.z + rv.z;
    v.w = sv.w * dinv + bv.w + rv.w;
    if (LEAKY) {
        v.x = v.x > 0.f ? v.x : 0.01f * v.x;
        v.y = v.y > 0.f ? v.y : 0.01f * v.y;
        v.z = v.z > 0.f ? v.z : 0.01f * v.z;
        v.w = v.w > 0.f ? v.w : 0.01f * v.w;
    }
    ((float4*)out)[gid] = v;
}

// ---- pipelined FFMA2 GEMM (R3 config): C[M,NC] = A[M,K] @ W[NC,K]^T --------
// HALF_OUT: write C as fp16 (half2-pair 8B stores) instead of fp32 float4.
template <int NC, bool FUSED, bool HALF_OUT>
__global__ __launch_bounds__(256, 2)
void gemm_kernel(const float* __restrict__ A, int K,
                 const float* __restrict__ A2,
                 const float* __restrict__ W,
                 void* __restrict__ Cout, int M) {
    constexpr int BM = 128, BK = 16;
    constexpr int WPT = NC / 64;
    constexpr int NG  = NC / 64;
    constexpr int CP2 = NC / 32;
    constexpr int WST = NC + 4;

    __shared__ float As[2][BM][BK + 4];
    __shared__ float Ws[2][BK][WST];

    int tid = threadIdx.x;
    int tx = tid & 15, ty = tid >> 4;
    int row0 = blockIdx.x * BM;
    int r0 = ty * 8;
    int c0 = tx * 4;

    unsigned long long acc2[8][CP2];
#pragma unroll
    for (int i = 0; i < 8; i++)
#pragma unroll
        for (int j = 0; j < CP2; j++) acc2[i][j] = 0ull;

    float4 ar[2], wr[WPT];
    int nch = K / BK;

    auto ldgA = [&](int ch) {
        int kk = ch * BK;
#pragma unroll
        for (int h = 0; h < 2; h++) {
            int f = tid + h * 256;
            int row = f >> 2;
            int kc = (f & 3) * 4;
            int grow = row0 + row;
            float4 v = make_float4(0.f, 0.f, 0.f, 0.f);
            if (grow < M) {
                if (!FUSED)
                    v = *(const float4*)(A + (size_t)grow * K + kk + kc);
                else if (kk < VT_DIM)
                    v = *(const float4*)(A + (size_t)grow * VT_DIM + kk + kc);
                else
                    v = *(const float4*)(A2 + (size_t)grow * CAT_DIM + (kk - VT_DIM) + kc);
            }
            ar[h] = v;
        }
    };
    auto ldgW = [&](int ch) {
        int kk = ch * BK;
#pragma unroll
        for (int h = 0; h < WPT; h++) {
            int f = tid + h * 256;
            int c = f >> 2;
            int kq = (f & 3) * 4;
            wr[h] = *(const float4*)(W + (size_t)c * K + kk + kq);
        }
    };
    auto sts = [&](int b) {
#pragma unroll
        for (int h = 0; h < 2; h++) {
            int f = tid + h * 256;
            *(float4*)&As[b][f >> 2][(f & 3) * 4] = ar[h];
        }
#pragma unroll
        for (int h = 0; h < WPT; h++) {
            int f = tid + h * 256;
            int c = f >> 2;
            int kq = (f & 3) * 4;
            Ws[b][kq + 0][c] = wr[h].x;
            Ws[b][kq + 1][c] = wr[h].y;
            Ws[b][kq + 2][c] = wr[h].z;
            Ws[b][kq + 3][c] = wr[h].w;
        }
    };
    auto compute = [&](int b) {
#pragma unroll
        for (int k2 = 0; k2 < BK; k2 += 2) {
            ulonglong2 w0[NG], w1[NG];
#pragma unroll
            for (int g = 0; g < NG; g++) {
                w0[g] = *(const ulonglong2*)&Ws[b][k2 + 0][c0 + g * 64];
                w1[g] = *(const ulonglong2*)&Ws[b][k2 + 1][c0 + g * 64];
            }
#pragma unroll
            for (int i = 0; i < 8; i++) {
                float2 t = *(const float2*)&As[b][r0 + i][k2];
                unsigned long long pa0 = pack_dup(t.x);
                unsigned long long pa1 = pack_dup(t.y);
#pragma unroll
                for (int g = 0; g < NG; g++) {
                    ffma2(acc2[i][2 * g + 0], pa0, w0[g].x);
                    ffma2(acc2[i][2 * g + 1], pa0, w0[g].y);
                    ffma2(acc2[i][2 * g + 0], pa1, w1[g].x);
                    ffma2(acc2[i][2 * g + 1], pa1, w1[g].y);
                }
            }
        }
    };

    ldgA(0); ldgW(0);
    sts(0);
    __syncthreads();

    for (int ch = 0; ch < nch; ch++) {
        int nb = ch & 1;
        if (ch + 1 < nch) { ldgA(ch + 1); ldgW(ch + 1); }
        compute(nb);
        if (ch + 1 < nch) sts(1 - nb);
        __syncthreads();
    }

#pragma unroll
    for (int i = 0; i < 8; i++) {
        int gr = row0 + r0 + i;
        if (gr >= M) continue;
#pragma unroll
        for (int g = 0; g < NG; g++) {
            int gc = c0 + g * 64;
            float4 v;
            unpack2(acc2[i][2 * g + 0], v.x, v.y);
            unpack2(acc2[i][2 * g + 1], v.z, v.w);
            if (HALF_OUT) {
                __half2 p0 = __floats2half2_rn(v.x, v.y);
                __half2 p1 = __floats2half2_rn(v.z, v.w);
                uint2 u;
                u.x = *(unsigned int*)&p0;
                u.y = *(unsigned int*)&p1;
                *(uint2*)((__half*)Cout + (size_t)gr * NC + gc) = u;
            } else {
                *(float4*)((float*)Cout + (size_t)gr * NC + gc) = v;
            }
        }
    }
}

// tiny no-op kernel used as a fork anchor on the capturing stream
__global__ void fork_kernel() {}

// ---------------- launch (R10 schedule) ----------------
extern "C" void kernel_launch(void* const* d_in, const int* in_sizes, int n_in,
                              void* d_out, int out_size) {
    const float* vt      = (const float*)d_in[0];
    const int*   cat_idx = (const int*)d_in[1];
    const int*   cat_off = (const int*)d_in[2];
    const int*   edge    = (const int*)d_in[3];
    const float* cat_tab = (const float*)d_in[4];
    const float* fuse_w  = (const float*)d_in[5];
    const float* user    = (const float*)d_in[6];
    const float* w1_l    = (const float*)d_in[7];
    const float* b1      = (const float*)d_in[8];
    const float* w1_r    = (const float*)d_in[9];
    const float* w2_l    = (const float*)d_in[10];
    const float* b2      = (const float*)d_in[11];
    const float* w2_r    = (const float*)d_in[12];

    int E = in_sizes[3] / 2;
    const int* src = edge;
    const int* dst = edge + E;
    int tot_idx = in_sizes[1];

    float *x0p, *s1p, *r1p, *x1p, *s2p, *r2p, *catp;
    __half *h1hp, *h2hp;
    cudaGetSymbolAddress((void**)&x0p, g_x0);
    cudaGetSymbolAddress((void**)&h1hp, g_h1h);
    cudaGetSymbolAddress((void**)&s1p, g_s1);
    cudaGetSymbolAddress((void**)&r1p, g_r1);
    cudaGetSymbolAddress((void**)&x1p, g_x1);
    cudaGetSymbolAddress((void**)&h2hp, g_h2h);
    cudaGetSymbolAddress((void**)&s2p, g_s2);
    cudaGetSymbolAddress((void**)&r2p, g_r2);
    cudaGetSymbolAddress((void**)&catp, g_cat);

    static cudaStream_t sB = nullptr;
    static cudaEvent_t eFork, eH1u, eH1i, eR1, eH2, eR2;
    if (!sB) {
        cudaStreamCreateWithFlags(&sB, cudaStreamNonBlocking);
        cudaEventCreateWithFlags(&eFork, cudaEventDisableTiming);
        cudaEventCreateWithFlags(&eH1u,  cudaEventDisableTiming);
        cudaEventCreateWithFlags(&eH1i,  cudaEventDisableTiming);
        cudaEventCreateWithFlags(&eR1,   cudaEventDisableTiming);
        cudaEventCreateWithFlags(&eH2,   cudaEventDisableTiming);
        cudaEventCreateWithFlags(&eR2,   cudaEventDisableTiming);
    }
    cudaStream_t sA = 0;   // origin (captured) stream

    const int grid_item = (ITEM_NUM + 127) / 128;   // 391
    const int grid_user = (USER_NUM + 127) / 128;   // 391
    const int grid_all  = (NTOT + 127) / 128;       // 782
    const int grid_c1   = (NTOT * (HID / 4) + 255) / 256;
    const int grid_c2   = (NTOT * (OUTD / 4) + 255) / 256;

    // ---- fork: sB joins the capture via an event recorded on sA ----
    fork_kernel<<<1, 32, 0, sA>>>();
    cudaEventRecord(eFork, sA);
    cudaStreamWaitEvent(sB, eFork, 0);

    // ---- side stream: init + CSR build, then user-row halves of h1/r1 ----
    init_kernel<<<1024, 256, 0, sB>>>(user);
    count_kernel<<<2048, 256, 0, sB>>>(dst, E);
    scan1_kernel<<<SCAN_NB, SCAN_B, 0, sB>>>();
    scan2_kernel<<<1, 256, 0, sB>>>();
    scan3_kernel<<<SCAN_NB, SCAN_B, 0, sB>>>();
    fill_kernel<<<2048, 256, 0, sB>>>(src, dst, E);
    gemm_kernel<128, false, true><<<grid_user, 256, 0, sB>>>(
        x0p, HID, nullptr, w1_l, h1hp, USER_NUM);
    cudaEventRecord(eH1u, sB);           // h1 user rows + CSR ready
    gemm_kernel<128, false, false><<<grid_user, 256, 0, sB>>>(
        x0p, HID, nullptr, w1_r, r1p, USER_NUM);

    // ---- main stream: features ----
    catbag_kernel<<<(ITEM_NUM * 8 + 255) / 256, 256, 0, sA>>>(cat_tab, cat_idx, cat_off, tot_idx);
    gemm_kernel<128, true, false><<<grid_item, 256, 0, sA>>>(
        vt, VT_DIM + CAT_DIM, catp, fuse_w, x0p + (size_t)USER_NUM * HID, ITEM_NUM);

    // ---- conv1 item halves + aggregate ----
    gemm_kernel<128, false, true><<<grid_item, 256, 0, sA>>>(
        x0p + (size_t)USER_NUM * HID, HID, nullptr, w1_l,
        h1hp + (size_t)USER_NUM * HID, ITEM_NUM);
    cudaEventRecord(eH1i, sA);

    cudaStreamWaitEvent(sB, eH1i, 0);    // x0 item rows ready (and h1 done)
    gemm_kernel<128, false, false><<<grid_item, 256, 0, sB>>>(
        x0p + (size_t)USER_NUM * HID, HID, nullptr, w1_r,
        r1p + (size_t)USER_NUM * HID, ITEM_NUM);
    cudaEventRecord(eR1, sB);

    cudaStreamWaitEvent(sA, eH1u, 0);    // h1 user rows + CSR ready
    agg_half_kernel<128><<<(NTOT * 16 + 255) / 256, 256, 0, sA>>>(h1hp, s1p);
    cudaStreamWaitEvent(sA, eR1, 0);
    combine_kernel<128, true><<<grid_c1, 256, 0, sA>>>(s1p, r1p, b1, x1p);

    // ---- conv2: h2 (fp16 out) alone; then agg2 (mem) ∥ r2 (compute) ----
    gemm_kernel<64, false, true><<<grid_all, 256, 0, sA>>>(
        x1p, HID, nullptr, w2_l, h2hp, NTOT);
    cudaEventRecord(eH2, sA);

    cudaStreamWaitEvent(sB, eH2, 0);     // x1 ready (combine1 precedes eH2 on sA)
    gemm_kernel<64, false, false><<<grid_all, 256, 0, sB>>>(
        x1p, HID, nullptr, w2_r, r2p, NTOT);
    cudaEventRecord(eR2, sB);

    agg_half_kernel<64><<<(NTOT * 8 + 255) / 256, 256, 0, sA>>>(h2hp, s2p);
    cudaStreamWaitEvent(sA, eR2, 0);     // join: sB fully merged back into sA
    combine_kernel<64, false><<<grid_c2, 256, 0, sA>>>(s2p, r2p, b2, (float*)d_out);
}